// round 10
// baseline (speedup 1.0000x reference)
#include <cuda_runtime.h>
#include <cstdint>
#include <math.h>

#define BATCH 4
#define SEQ   2048
#define HID   1024
#define DIM   1024
#define SCALE 0.03125f
#define QMAXF 32512.0f
#define RX 6.0f
#define RW 0.1875f
#define RQ 8.0f

#define NSTG  3
#define ASTRB 80
#define ATILE (128*ASTRB)
#define BTILE (64*ASTRB)
#define STGB  (2*ATILE+2*BTILE)
#define SMEMB (NSTG*STGB)

// device-global scratch
__device__ float  g_P [(long)BATCH*SEQ*SEQ];
__device__ float  g_rs[(long)BATCH*SEQ];
__device__ float  g_Vf[(long)BATCH*SEQ*DIM];
__device__ int8_t g_X1[(long)BATCH*SEQ*HID], g_X2[(long)BATCH*SEQ*HID];
__device__ int8_t g_W1[(long)3*DIM*HID],     g_W2[(long)3*DIM*HID];
__device__ int8_t g_Q1[(long)BATCH*SEQ*DIM], g_Q2[(long)BATCH*SEQ*DIM];
__device__ int8_t g_K1[(long)BATCH*SEQ*DIM], g_K2[(long)BATCH*SEQ*DIM];
__device__ int8_t g_V1[(long)BATCH*DIM*SEQ], g_V2[(long)BATCH*DIM*SEQ];
__device__ int8_t g_P1[(long)BATCH*SEQ*SEQ], g_P2[(long)BATCH*SEQ*SEQ];

// ---------------- PTX helpers (baseline sm_80-level) ----------------
__device__ __forceinline__ uint32_t smem_u32(const void* p) {
    uint32_t a;
    asm("{ .reg .u64 t; cvta.to.shared.u64 t, %1; cvt.u32.u64 %0, t; }"
        : "=r"(a) : "l"(p));
    return a;
}
__device__ __forceinline__ void cpa16(uint32_t dst, const void* src) {
    asm volatile("cp.async.cg.shared.global [%0], [%1], 16;" :: "r"(dst), "l"(src));
}
#define CP_COMMIT() asm volatile("cp.async.commit_group;" ::: "memory")
#define CP_WAIT1()  asm volatile("cp.async.wait_group 1;" ::: "memory")

__device__ __forceinline__ void ldsm_x4(uint32_t* r, uint32_t addr) {
    asm volatile("ldmatrix.sync.aligned.m8n8.x4.shared.b16 {%0,%1,%2,%3}, [%4];"
                 : "=r"(r[0]), "=r"(r[1]), "=r"(r[2]), "=r"(r[3]) : "r"(addr));
}
__device__ __forceinline__ void mma_s8(int* c, const uint32_t* a, const uint32_t* b) {
    asm volatile(
        "mma.sync.aligned.m16n8k32.row.col.s32.s8.s8.s32 "
        "{%0,%1,%2,%3}, {%4,%5,%6,%7}, {%8,%9}, {%0,%1,%2,%3};"
        : "+r"(c[0]), "+r"(c[1]), "+r"(c[2]), "+r"(c[3])
        : "r"(a[0]), "r"(a[1]), "r"(a[2]), "r"(a[3]), "r"(b[0]), "r"(b[1]));
}

// quantize one fp32 to 16-bit fixed point split into hi/lo int8 (v = 256h + l)
__device__ __forceinline__ void q16(float x, float qm, int8_t* hi, int8_t* lo) {
    float xv = fminf(fmaxf(x * qm, -QMAXF), QMAXF);
    int v = __float2int_rn(xv);
    int h = (v + 128) >> 8;
    *hi = (int8_t)h;
    *lo = (int8_t)(v - (h << 8));
}
__device__ __forceinline__ void qout2(int8_t* d1, int8_t* d2, long idx,
                                      float a, float b, float qm) {
    int8_t ha, la, hb, lb;
    q16(a, qm, &ha, &la);
    q16(b, qm, &hb, &lb);
    *(short*)(d1 + idx) = (short)(((uint8_t)ha) | (((uint16_t)(uint8_t)hb) << 8));
    *(short*)(d2 + idx) = (short)(((uint8_t)la) | (((uint16_t)(uint8_t)lb) << 8));
}

// ---------------- quantization kernels ----------------
__global__ __launch_bounds__(256)
void quant_lin(const float* __restrict__ src, int8_t* __restrict__ d1,
               int8_t* __restrict__ d2, long n, float qm)
{
    long i = blockIdx.x * 256 + threadIdx.x;
    long stride = (long)gridDim.x * 256;
    for (; i < n; i += stride) {
        float2 v = *(const float2*)(src + i * 2);
        qout2(d1, d2, i * 2, v.x, v.y, qm);
    }
}

// transpose + quantize: src [R][C] fp32 -> dst [C][R] int8 pairs
// FIX (R9 bug): write t[tx][y'] to dst[c0+y'][r0+tx] (value/index roles were
// swapped, scrambling every 32x32 tile of W^T and V^T).
__global__ __launch_bounds__(256)
void quant_T(const float* __restrict__ src, int8_t* __restrict__ d1,
             int8_t* __restrict__ d2, int R, int C, float qm, long batchR)
{
    __shared__ float t[32][33];
    const int tx = threadIdx.x & 31, ty = threadIdx.x >> 5;  // 32 x 8
    const int c0 = blockIdx.x * 32, r0 = blockIdx.y * 32;
    src += blockIdx.z * batchR * C;
    d1  += blockIdx.z * (long)C * batchR;
    d2  += blockIdx.z * (long)C * batchR;
    #pragma unroll
    for (int i = 0; i < 4; ++i)
        t[ty + 8 * i][tx] = src[(long)(r0 + ty + 8 * i) * C + c0 + tx];
    __syncthreads();
    #pragma unroll
    for (int i = 0; i < 4; ++i) {
        int8_t hi, lo;
        q16(t[tx][ty + 8 * i], qm, &hi, &lo);
        long idx = (long)(c0 + ty + 8 * i) * R + r0 + tx;   // coalesced in tx
        d1[idx] = hi;
        d2[idx] = lo;
    }
}

// ---------------- int8 NT GEMM core ----------------
// A: [M][K] pairs (rows m0..m0+127), B: [N][K] pairs (rows n0..n0+63).
// smem: A 128x64B stride 80, B 64x64B stride 80, per hi/lo array.
// 8 warps (4m x 2n), warp tile 32x32. facc[8][4]: fi = mt*4 + np*2 + h.
__device__ __forceinline__ void tile_i8(float facc[8][4], uint32_t a1S, uint32_t a2S,
                                        uint32_t b1S, uint32_t b2S, int wm, int wn,
                                        int lane)
{
    const int arow = (lane & 7) + ((lane >> 3) & 1) * 8;
    const int abyt = (lane >> 4) * 16;
    const int brow = (lane & 7) + ((lane >> 4) & 1) * 8;
    const int bbyt = ((lane >> 3) & 1) * 16;
    #pragma unroll
    for (int ks = 0; ks < 2; ++ks) {
        uint32_t a1[2][4], a2[2][4];
        #pragma unroll
        for (int mt = 0; mt < 2; ++mt) {
            uint32_t off = (uint32_t)(wm + mt * 16 + arow) * ASTRB + ks * 32 + abyt;
            ldsm_x4(a1[mt], a1S + off);
            ldsm_x4(a2[mt], a2S + off);
        }
        #pragma unroll
        for (int np = 0; np < 2; ++np) {
            uint32_t b1[4], b2[4];
            uint32_t off = (uint32_t)(wn + np * 16 + brow) * ASTRB + ks * 32 + bbyt;
            ldsm_x4(b1, b1S + off);
            ldsm_x4(b2, b2S + off);
            #pragma unroll
            for (int mt = 0; mt < 2; ++mt) {
                #pragma unroll
                for (int h = 0; h < 2; ++h) {
                    int c11[4] = {0,0,0,0}, cx[4] = {0,0,0,0}, c22[4] = {0,0,0,0};
                    mma_s8(c11, a1[mt], b1 + h * 2);
                    mma_s8(cx,  a1[mt], b2 + h * 2);
                    mma_s8(cx,  a2[mt], b1 + h * 2);
                    mma_s8(c22, a2[mt], b2 + h * 2);
                    float* f = facc[mt * 4 + np * 2 + h];
                    #pragma unroll
                    for (int e = 0; e < 4; ++e)
                        f[e] += 65536.f * (float)c11[e] + 256.f * (float)cx[e]
                                + (float)c22[e];
                }
            }
        }
    }
}

#define GEMM_PROLOGUE()                                                     \
    extern __shared__ int8_t smem[];                                        \
    const int tid = threadIdx.x, lane = tid & 31;                           \
    const int wm = ((tid >> 5) & 3) * 32, wn = (tid >> 7) * 32;             \
    uint32_t a1S[NSTG], a2S[NSTG], b1S[NSTG], b2S[NSTG];                    \
    _Pragma("unroll")                                                       \
    for (int s = 0; s < NSTG; ++s) {                                        \
        uint32_t base = smem_u32(smem + s * STGB);                          \
        a1S[s] = base;             a2S[s] = base + ATILE;                   \
        b1S[s] = base + 2 * ATILE; b2S[s] = base + 2 * ATILE + BTILE;       \
    }                                                                       \
    float facc[8][4];                                                       \
    _Pragma("unroll")                                                       \
    for (int i = 0; i < 8; ++i)                                             \
        _Pragma("unroll")                                                   \
        for (int e = 0; e < 4; ++e) facc[i][e] = 0.f;

#define GEMM_ISSUE(A1, A2, B1, B2, LDA, LDB, KEND)                          \
    auto issue = [&](int kt, int s) {                                       \
        if (kt < (KEND)) {                                                  \
            _Pragma("unroll")                                               \
            for (int i = 0; i < 2; ++i) {                                   \
                int q = tid + i * 256;                                      \
                int r = q >> 2, cb = (q & 3) * 16;                          \
                uint32_t doff = (uint32_t)r * ASTRB + cb;                   \
                cpa16(a1S[s] + doff, (A1) + (long)(m0 + r) * (LDA) + kt + cb); \
                cpa16(a2S[s] + doff, (A2) + (long)(m0 + r) * (LDA) + kt + cb); \
            }                                                               \
            int r = tid >> 2, cb = (tid & 3) * 16;                          \
            uint32_t doff = (uint32_t)r * ASTRB + cb;                       \
            cpa16(b1S[s] + doff, (B1) + (long)(n0 + r) * (LDB) + kt + cb);  \
            cpa16(b2S[s] + doff, (B2) + (long)(n0 + r) * (LDB) + kt + cb);  \
        }                                                                   \
        CP_COMMIT();                                                        \
    };

#define GEMM_MAINLOOP(KEND, ACTIVE)                                         \
    issue(0, 0);                                                            \
    issue(64, 1);                                                           \
    {                                                                       \
        int s = 0;                                                          \
        for (int kt = 0; kt < (KEND); kt += 64) {                           \
            CP_WAIT1();                                                     \
            __syncthreads();                                                \
            issue(kt + 128, (s + 2) % NSTG);                                \
            if (ACTIVE)                                                     \
                tile_i8(facc, a1S[s], a2S[s], b1S[s], b2S[s], wm, wn, lane);\
            s = (s + 1) % NSTG;                                             \
            __syncthreads();                                                \
        }                                                                   \
    }

// ---------------- merged QKV projection ----------------
// A = X pairs [8192][1024]; B = W^T pairs (3 stacked) [D][H]. NT.
__global__ __launch_bounds__(256)
void gemm_qkv(const int8_t* __restrict__ X1, const int8_t* __restrict__ X2,
              const int8_t* __restrict__ W1, const int8_t* __restrict__ W2,
              int8_t* __restrict__ Q1, int8_t* __restrict__ Q2,
              int8_t* __restrict__ K1, int8_t* __restrict__ K2,
              float* __restrict__ Vf)
{
    const int wsel = blockIdx.x >> 4;
    const int n0 = (blockIdx.x & 15) * 64;
    const int m0 = blockIdx.y * 128;
    const int8_t* B1 = W1 + (long)wsel * DIM * HID;
    const int8_t* B2 = W2 + (long)wsel * DIM * HID;

    GEMM_PROLOGUE();
    GEMM_ISSUE(X1, X2, B1, B2, HID, HID, HID);
    GEMM_MAINLOOP(HID, true);

    const float deq = (RX * RW) / (QMAXF * QMAXF);
    const float qm = QMAXF / RQ;
    int8_t* O1 = (wsel == 0) ? Q1 : K1;
    int8_t* O2 = (wsel == 0) ? Q2 : K2;
    #pragma unroll
    for (int mt = 0; mt < 2; ++mt) {
        #pragma unroll
        for (int j = 0; j < 4; ++j) {
            float* f = facc[mt * 4 + j];
            int row = m0 + wm + mt * 16 + (lane >> 2);
            int col = n0 + wn + j * 8 + (lane & 3) * 2;
            float c0 = f[0] * deq, c1 = f[1] * deq;
            float c2 = f[2] * deq, c3 = f[3] * deq;
            if (wsel == 2) {
                *(float2*)(Vf + (long)row * DIM + col) = make_float2(c0, c1);
                *(float2*)(Vf + (long)(row + 8) * DIM + col) = make_float2(c2, c3);
            } else {
                qout2(O1, O2, (long)row * DIM + col, c0, c1, qm);
                qout2(O1, O2, (long)(row + 8) * DIM + col, c2, c3, qm);
            }
        }
    }
}

// ---------------- scores GEMM (NT, causal) ----------------
__global__ __launch_bounds__(256)
void gemm_scores(const int8_t* __restrict__ Q1, const int8_t* __restrict__ Q2,
                 const int8_t* __restrict__ K1, const int8_t* __restrict__ K2,
                 float* __restrict__ P)
{
    const int m0 = blockIdx.y * 128;
    const int n0 = blockIdx.x * 64;
    if (n0 > m0 + 127) return;
    const long zq = (long)blockIdx.z * SEQ * DIM;
    const int8_t* A1 = Q1 + zq; const int8_t* A2 = Q2 + zq;
    const int8_t* B1 = K1 + zq; const int8_t* B2 = K2 + zq;
    P += (long)blockIdx.z * SEQ * SEQ;

    GEMM_PROLOGUE();
    const bool active = (n0 + wn) <= (m0 + wm + 31);
    GEMM_ISSUE(A1, A2, B1, B2, DIM, DIM, DIM);
    GEMM_MAINLOOP(DIM, active);

    if (active) {
        const float deq = (RQ * RQ) / (QMAXF * QMAXF) * SCALE;
        #pragma unroll
        for (int mt = 0; mt < 2; ++mt) {
            #pragma unroll
            for (int j = 0; j < 4; ++j) {
                float* f = facc[mt * 4 + j];
                int row = m0 + wm + mt * 16 + (lane >> 2);
                int col = n0 + wn + j * 8 + (lane & 3) * 2;
                *(float2*)(P + (long)row * SEQ + col) =
                    make_float2(f[0] * deq, f[1] * deq);
                *(float2*)(P + (long)(row + 8) * SEQ + col) =
                    make_float2(f[2] * deq, f[3] * deq);
            }
        }
    }
}

// ---------------- PV GEMM (NT vs V^T, K bounded) ----------------
__global__ __launch_bounds__(256)
void gemm_pv(const int8_t* __restrict__ P1, const int8_t* __restrict__ P2,
             const int8_t* __restrict__ V1, const int8_t* __restrict__ V2,
             const float* __restrict__ rs, float* __restrict__ Out)
{
    const int m0 = blockIdx.y * 128;
    const int n0 = blockIdx.x * 64;
    const int8_t* A1 = P1 + (long)blockIdx.z * SEQ * SEQ;
    const int8_t* A2 = P2 + (long)blockIdx.z * SEQ * SEQ;
    const int8_t* B1 = V1 + (long)blockIdx.z * DIM * SEQ;
    const int8_t* B2 = V2 + (long)blockIdx.z * DIM * SEQ;
    rs += (long)blockIdx.z * SEQ;
    Out += (long)blockIdx.z * SEQ * DIM;
    const int kEnd = m0 + 128;

    GEMM_PROLOGUE();
    GEMM_ISSUE(A1, A2, B1, B2, SEQ, SEQ, kEnd);
    GEMM_MAINLOOP(kEnd, true);

    const float deq = RQ / (QMAXF * QMAXF);
    #pragma unroll
    for (int mt = 0; mt < 2; ++mt) {
        int row = m0 + wm + mt * 16 + (lane >> 2);
        float s0 = rs[row] * deq;
        float s1 = rs[row + 8] * deq;
        #pragma unroll
        for (int j = 0; j < 4; ++j) {
            float* f = facc[mt * 4 + j];
            int col = n0 + wn + j * 8 + (lane & 3) * 2;
            *(float2*)(Out + (long)row * DIM + col) =
                make_float2(f[0] * s0, f[1] * s0);
            *(float2*)(Out + (long)(row + 8) * DIM + col) =
                make_float2(f[2] * s1, f[3] * s1);
        }
    }
}

// ---------------- causal softmax -> quantized e + row scale ----------------
__global__ __launch_bounds__(256)
void softmax_causal(const float* __restrict__ P, int8_t* __restrict__ P1,
                    int8_t* __restrict__ P2, float* __restrict__ rs)
{
    const int S = SEQ;
    const int i = blockIdx.x, b = blockIdx.y;
    const float* row = P + ((long)b * S + i) * S;
    int8_t* r1 = P1 + ((long)b * S + i) * S;
    int8_t* r2 = P2 + ((long)b * S + i) * S;

    __shared__ float buf[SEQ];
    __shared__ float red[256];
    const int tid = threadIdx.x;
    const int L = i + 1;

    float m = -3.0e38f;
    for (int j = tid; j < L; j += 256) {
        float v = row[j];
        buf[j] = v;
        m = fmaxf(m, v);
    }
    red[tid] = m;
    __syncthreads();
    #pragma unroll
    for (int sd = 128; sd > 0; sd >>= 1) {
        if (tid < sd) red[tid] = fmaxf(red[tid], red[tid + sd]);
        __syncthreads();
    }
    m = red[0];
    __syncthreads();

    float sum = 0.f;
    for (int j = tid; j < L; j += 256) {
        float e = expf(buf[j] - m);
        buf[j] = e;
        sum += e;
    }
    red[tid] = sum;
    __syncthreads();
    #pragma unroll
    for (int sd = 128; sd > 0; sd >>= 1) {
        if (tid < sd) red[tid] += red[tid + sd];
        __syncthreads();
    }
    const float inv = 1.0f / red[0];
    if (tid == 0) rs[(long)b * S + i] = inv;

    for (int j = tid; j < S; j += 256) {
        float e = (j < L) ? buf[j] : 0.f;
        int v = __float2int_rn(e * QMAXF);
        int h = (v + 128) >> 8;
        r1[j] = (int8_t)h;
        r2[j] = (int8_t)(v - (h << 8));
    }
}

// ---------------------------------------------------------------------------
extern "C" void kernel_launch(void* const* d_in, const int* in_sizes, int n_in,
                              void* d_out, int out_size)
{
    (void)in_sizes; (void)n_in; (void)out_size;
    const float* X  = (const float*)d_in[0];
    const float* Wq = (const float*)d_in[1];
    const float* Wk = (const float*)d_in[2];
    const float* Wv = (const float*)d_in[3];
    float* out = (float*)d_out;

    #define SYM(v, s) void* v; cudaGetSymbolAddress(&v, s)
    SYM(pP, g_P); SYM(pRs, g_rs); SYM(pVf, g_Vf);
    SYM(pX1, g_X1); SYM(pX2, g_X2);
    SYM(pW1, g_W1); SYM(pW2, g_W2);
    SYM(pQ1, g_Q1); SYM(pQ2, g_Q2);
    SYM(pK1, g_K1); SYM(pK2, g_K2);
    SYM(pV1, g_V1); SYM(pV2, g_V2);
    SYM(pP1, g_P1); SYM(pP2, g_P2);
    #undef SYM

    cudaFuncSetAttribute(gemm_qkv, cudaFuncAttributeMaxDynamicSharedMemorySize, SMEMB);
    cudaFuncSetAttribute(gemm_scores, cudaFuncAttributeMaxDynamicSharedMemorySize, SMEMB);
    cudaFuncSetAttribute(gemm_pv, cudaFuncAttributeMaxDynamicSharedMemorySize, SMEMB);

    // 0) quantize X (linear) and W's (transposed into [D][H])
    quant_lin<<<2048, 256>>>(X, (int8_t*)pX1, (int8_t*)pX2,
                             (long)BATCH * SEQ * HID / 2, QMAXF / RX);
    {
        dim3 g(DIM / 32, HID / 32, 1);
        quant_T<<<g, 256>>>(Wq, (int8_t*)pW1, (int8_t*)pW2,
                            HID, DIM, QMAXF / RW, HID);
        quant_T<<<g, 256>>>(Wk, (int8_t*)pW1 + (long)DIM * HID,
                            (int8_t*)pW2 + (long)DIM * HID,
                            HID, DIM, QMAXF / RW, HID);
        quant_T<<<g, 256>>>(Wv, (int8_t*)pW1 + 2L * DIM * HID,
                            (int8_t*)pW2 + 2L * DIM * HID,
                            HID, DIM, QMAXF / RW, HID);
    }

    // 1) merged QKV projections (Q,K -> int8 pairs; V -> fp32)
    {
        dim3 grid(48, (BATCH * SEQ) / 128, 1);
        gemm_qkv<<<grid, 256, SMEMB>>>(
            (int8_t*)pX1, (int8_t*)pX2, (int8_t*)pW1, (int8_t*)pW2,
            (int8_t*)pQ1, (int8_t*)pQ2, (int8_t*)pK1, (int8_t*)pK2,
            (float*)pVf);
    }

    // 1b) V fp32 [S][D] -> V^T int8 pairs [D][S] per batch
    {
        dim3 g(DIM / 32, SEQ / 32, BATCH);
        quant_T<<<g, 256>>>((float*)pVf, (int8_t*)pV1, (int8_t*)pV2,
                            SEQ, DIM, QMAXF / RQ, SEQ);
    }

    // 2) scores = (Q K^T) * SCALE, causal blocks only
    {
        dim3 grid(SEQ / 64, SEQ / 128, BATCH);
        gemm_scores<<<grid, 256, SMEMB>>>(
            (int8_t*)pQ1, (int8_t*)pQ2, (int8_t*)pK1, (int8_t*)pK2, (float*)pP);
    }

    // 3) softmax -> quantized e rows + per-row 1/sum
    {
        dim3 grid(SEQ, BATCH);
        softmax_causal<<<grid, 256>>>((float*)pP, (int8_t*)pP1, (int8_t*)pP2,
                                      (float*)pRs);
    }

    // 4) out = P V, K bounded by causality
    {
        dim3 grid(DIM / 64, SEQ / 128, BATCH);
        gemm_pv<<<grid, 256, SMEMB>>>(
            (int8_t*)pP1, (int8_t*)pP2, (int8_t*)pV1, (int8_t*)pV2,
            (float*)pRs, out);
    }
}

// round 11
// speedup vs baseline: 4.4168x; 4.4168x over previous
#include <cuda_runtime.h>
#include <cuda_bf16.h>
#include <cuda_fp16.h>
#include <cstdint>
#include <math.h>

#define BATCH 4
#define SEQ   2048
#define HID   1024
#define DIM   1024
#define SCALE 0.03125f   // 1/sqrt(1024)

typedef __nv_bfloat16 bf16;
typedef __nv_bfloat162 bf162;

// Scratch (device globals; runtime allocation is forbidden)
__device__ float g_P[(long)BATCH * SEQ * SEQ];
__device__ bf16 g_Xhi[(long)BATCH * SEQ * HID];
__device__ bf16 g_Xlo[(long)BATCH * SEQ * HID];
__device__ bf16 g_Wqh[(long)HID * DIM];
__device__ bf16 g_Wql[(long)HID * DIM];
__device__ bf16 g_Wkh[(long)HID * DIM];
__device__ bf16 g_Wkl[(long)HID * DIM];
__device__ bf16 g_Wvh[(long)HID * DIM];
__device__ bf16 g_Wvl[(long)HID * DIM];
__device__ __half g_Qh[(long)BATCH * SEQ * DIM];
__device__ __half g_Kh[(long)BATCH * SEQ * DIM];
__device__ __half g_Vh[(long)BATCH * SEQ * DIM];
__device__ __half g_Ph[(long)BATCH * SEQ * SEQ];

// ---------------------------------------------------------------------------
// PTX helpers (baseline sm_80-level PTX)
// ---------------------------------------------------------------------------
__device__ __forceinline__ uint32_t smem_u32(const void* p) {
    uint32_t a;
    asm("{ .reg .u64 t; cvta.to.shared.u64 t, %1; cvt.u32.u64 %0, t; }"
        : "=r"(a) : "l"(p));
    return a;
}
__device__ __forceinline__ void cpa16(uint32_t dst, const void* src) {
    asm volatile("cp.async.cg.shared.global [%0], [%1], 16;" :: "r"(dst), "l"(src));
}
#define CP_COMMIT() asm volatile("cp.async.commit_group;" ::: "memory")
#define CP_WAIT1()  asm volatile("cp.async.wait_group 1;" ::: "memory")

__device__ __forceinline__ void ldsm_x4(uint32_t* r, uint32_t addr) {
    asm volatile("ldmatrix.sync.aligned.m8n8.x4.shared.b16 {%0,%1,%2,%3}, [%4];"
                 : "=r"(r[0]), "=r"(r[1]), "=r"(r[2]), "=r"(r[3]) : "r"(addr));
}
__device__ __forceinline__ void ldsm_x4_t(uint32_t* r, uint32_t addr) {
    asm volatile("ldmatrix.sync.aligned.m8n8.x4.trans.shared.b16 {%0,%1,%2,%3}, [%4];"
                 : "=r"(r[0]), "=r"(r[1]), "=r"(r[2]), "=r"(r[3]) : "r"(addr));
}
__device__ __forceinline__ void mma_bf16(float* c, const uint32_t* a,
                                         const uint32_t* b) {
    asm volatile(
        "mma.sync.aligned.m16n8k16.row.col.f32.bf16.bf16.f32 "
        "{%0,%1,%2,%3}, {%4,%5,%6,%7}, {%8,%9}, {%0,%1,%2,%3};"
        : "+f"(c[0]), "+f"(c[1]), "+f"(c[2]), "+f"(c[3])
        : "r"(a[0]), "r"(a[1]), "r"(a[2]), "r"(a[3]), "r"(b[0]), "r"(b[1]));
}
__device__ __forceinline__ void mma_f16(float* c, const uint32_t* a,
                                        const uint32_t* b) {
    asm volatile(
        "mma.sync.aligned.m16n8k16.row.col.f32.f16.f16.f32 "
        "{%0,%1,%2,%3}, {%4,%5,%6,%7}, {%8,%9}, {%0,%1,%2,%3};"
        : "+f"(c[0]), "+f"(c[1]), "+f"(c[2]), "+f"(c[3])
        : "r"(a[0]), "r"(a[1]), "r"(a[2]), "r"(a[3]), "r"(b[0]), "r"(b[1]));
}

// ---------------------------------------------------------------------------
// fp32 -> (hi, lo) bf16 split, elementwise (n multiple of 4)
// ---------------------------------------------------------------------------
__global__ __launch_bounds__(256)
void split_fp32(const float* __restrict__ src, bf16* __restrict__ hi,
                bf16* __restrict__ lo, long n4)
{
    long i = blockIdx.x * 256 + threadIdx.x;
    long stride = (long)gridDim.x * 256;
    for (; i < n4; i += stride) {
        float4 v = *(const float4*)(src + i * 4);
        bf16 hx = __float2bfloat16(v.x), hy = __float2bfloat16(v.y);
        bf16 hz = __float2bfloat16(v.z), hw = __float2bfloat16(v.w);
        bf162 h0 = __halves2bfloat162(hx, hy);
        bf162 h1 = __halves2bfloat162(hz, hw);
        bf162 l0 = __halves2bfloat162(__float2bfloat16(v.x - __bfloat162float(hx)),
                                      __float2bfloat16(v.y - __bfloat162float(hy)));
        bf162 l1 = __halves2bfloat162(__float2bfloat16(v.z - __bfloat162float(hz)),
                                      __float2bfloat16(v.w - __bfloat162float(hw)));
        uint2 hu, lu;
        hu.x = reinterpret_cast<uint32_t&>(h0); hu.y = reinterpret_cast<uint32_t&>(h1);
        lu.x = reinterpret_cast<uint32_t&>(l0); lu.y = reinterpret_cast<uint32_t&>(l1);
        *(uint2*)(hi + i * 4) = hu;
        *(uint2*)(lo + i * 4) = lu;
    }
}

// ---------------------------------------------------------------------------
// Tiling config: BM=BN=128, BK=32, 256 threads, 8 warps (4m x 2n),
// warp tile 32x64. 3-stage cp.async pipeline.
// ---------------------------------------------------------------------------
#define ASTR 40    // 16-bit row stride A / B(NT): 80B, ldmatrix conflict-free
#define BSTR 136   // 16-bit row stride B(NN) [k][n]: 272B, conflict-free
#define NSTG 3

// 3-term bf16 Markidis tile (QKV projections)
__device__ __forceinline__ void mma_tile3(
    float acc[2][8][4], uint32_t aHi, uint32_t aLo, uint32_t bHi, uint32_t bLo,
    int wm, int wn, int lane)
{
    #pragma unroll
    for (int ks = 0; ks < 2; ++ks) {
        uint32_t aH[2][4], aL[2][4];
        #pragma unroll
        for (int mt = 0; mt < 2; ++mt) {
            uint32_t off =
                ((uint32_t)(wm + mt * 16 + (lane & 15)) * ASTR +
                 ks * 16 + (lane >> 4) * 8) * 2;
            ldsm_x4(aH[mt], aHi + off);
            ldsm_x4(aL[mt], aLo + off);
        }
        #pragma unroll
        for (int np = 0; np < 4; ++np) {
            uint32_t bH[4], bL[4];
            // NN path: B tile is [k][n] stride BSTR
            uint32_t krow = ks * 16 + (lane & 15);
            uint32_t ncol = wn + np * 16 + (lane >> 4) * 8;
            uint32_t off = (krow * BSTR + ncol) * 2;
            ldsm_x4_t(bH, bHi + off);
            ldsm_x4_t(bL, bLo + off);
            #pragma unroll
            for (int h = 0; h < 2; ++h) {
                #pragma unroll
                for (int mt = 0; mt < 2; ++mt) {
                    float* c = acc[mt][np * 2 + h];
                    mma_bf16(c, aH[mt], bH + h * 2);
                    mma_bf16(c, aH[mt], bL + h * 2);
                    mma_bf16(c, aL[mt], bH + h * 2);
                }
            }
        }
    }
}

// single-pass fp16 tile
template <bool TRANSB>
__device__ __forceinline__ void mma_tile1(
    float acc[2][8][4], uint32_t aS, uint32_t bS, int wm, int wn, int lane)
{
    #pragma unroll
    for (int ks = 0; ks < 2; ++ks) {
        uint32_t aF[2][4];
        #pragma unroll
        for (int mt = 0; mt < 2; ++mt) {
            uint32_t off =
                ((uint32_t)(wm + mt * 16 + (lane & 15)) * ASTR +
                 ks * 16 + (lane >> 4) * 8) * 2;
            ldsm_x4(aF[mt], aS + off);
        }
        #pragma unroll
        for (int np = 0; np < 4; ++np) {
            uint32_t bF[4];
            if (TRANSB) {
                uint32_t nrow = wn + np * 16 + (lane & 7) + (lane >> 4) * 8;
                uint32_t off = (nrow * ASTR + ks * 16 + ((lane >> 3) & 1) * 8) * 2;
                ldsm_x4(bF, bS + off);
            } else {
                uint32_t krow = ks * 16 + (lane & 15);
                uint32_t ncol = wn + np * 16 + (lane >> 4) * 8;
                uint32_t off = (krow * BSTR + ncol) * 2;
                ldsm_x4_t(bF, bS + off);
            }
            #pragma unroll
            for (int h = 0; h < 2; ++h) {
                #pragma unroll
                for (int mt = 0; mt < 2; ++mt)
                    mma_f16(acc[mt][np * 2 + h], aF[mt], bF + h * 2);
            }
        }
    }
}

#define ACC_DECL()                                                          \
    float acc[2][8][4];                                                     \
    _Pragma("unroll")                                                       \
    for (int i_ = 0; i_ < 2; ++i_)                                          \
        _Pragma("unroll")                                                   \
        for (int j_ = 0; j_ < 8; ++j_)                                      \
            _Pragma("unroll")                                               \
            for (int t_ = 0; t_ < 4; ++t_) acc[i_][j_][t_] = 0.f;

// ---------------------------------------------------------------------------
// Merged QKV projection (3-term bf16): grid (24, 64). bx>>3 selects output.
// Epilogue writes single fp16 Q/K/V.
// ---------------------------------------------------------------------------
__global__ __launch_bounds__(256)
void gemm_qkv(const bf16* __restrict__ Xhi, const bf16* __restrict__ Xlo,
              const bf16* __restrict__ W0h, const bf16* __restrict__ W0l,
              const bf16* __restrict__ W1h, const bf16* __restrict__ W1l,
              const bf16* __restrict__ W2h, const bf16* __restrict__ W2l,
              __half* __restrict__ Qh, __half* __restrict__ Kh,
              __half* __restrict__ Vh)
{
    constexpr int ASZ = 128 * ASTR;
    constexpr int BSZ = 32 * BSTR;
    constexpr int STG = 2 * ASZ + 2 * BSZ;
    extern __shared__ bf16 smem[];

    const int wsel = blockIdx.x >> 3;
    const int n0 = (blockIdx.x & 7) * 128;
    const int m0 = blockIdx.y * 128;

    const bf16* Bhi = (wsel == 0) ? W0h : (wsel == 1) ? W1h : W2h;
    const bf16* Blo = (wsel == 0) ? W0l : (wsel == 1) ? W1l : W2l;
    __half* Out = (wsel == 0) ? Qh : (wsel == 1) ? Kh : Vh;

    const int tid  = threadIdx.x;
    const int lane = tid & 31;
    const int wm   = ((tid >> 5) & 3) * 32;
    const int wn   = (tid >> 7) * 64;

    uint32_t aHiS[NSTG], aLoS[NSTG], bHiS[NSTG], bLoS[NSTG];
    #pragma unroll
    for (int s = 0; s < NSTG; ++s) {
        uint32_t base = smem_u32(smem + s * STG);
        aHiS[s] = base;
        aLoS[s] = base + ASZ * 2;
        bHiS[s] = base + 2 * ASZ * 2;
        bLoS[s] = base + (2 * ASZ + BSZ) * 2;
    }

    auto issue = [&](int kt, int s) {
        if (kt < HID) {
            #pragma unroll
            for (int i = 0; i < 2; ++i) {
                int q = tid + i * 256;
                int r = q >> 2, c = (q & 3) * 8;
                uint32_t doff = (uint32_t)(r * ASTR + c) * 2;
                cpa16(aHiS[s] + doff, Xhi + (long)(m0 + r) * HID + kt + c);
                cpa16(aLoS[s] + doff, Xlo + (long)(m0 + r) * HID + kt + c);
                int kk = q >> 4, nn = (q & 15) * 8;
                uint32_t boff = (uint32_t)(kk * BSTR + nn) * 2;
                cpa16(bHiS[s] + boff, Bhi + (long)(kt + kk) * DIM + n0 + nn);
                cpa16(bLoS[s] + boff, Blo + (long)(kt + kk) * DIM + n0 + nn);
            }
        }
        CP_COMMIT();
    };

    ACC_DECL();
    issue(0, 0);
    issue(32, 1);

    int s = 0;
    for (int kt = 0; kt < HID; kt += 32) {
        CP_WAIT1();
        __syncthreads();
        issue(kt + 64, (s + 2) % NSTG);
        mma_tile3(acc, aHiS[s], aLoS[s], bHiS[s], bLoS[s], wm, wn, lane);
        s = (s + 1) % NSTG;
        __syncthreads();
    }

    #pragma unroll
    for (int mt = 0; mt < 2; ++mt) {
        #pragma unroll
        for (int nt = 0; nt < 8; ++nt) {
            int row = m0 + wm + mt * 16 + (lane >> 2);
            int col = n0 + wn + nt * 8 + (lane & 3) * 2;
            float* f = acc[mt][nt];
            *(__half2*)(Out + (long)row * DIM + col) =
                __floats2half2_rn(f[0], f[1]);
            *(__half2*)(Out + (long)(row + 8) * DIM + col) =
                __floats2half2_rn(f[2], f[3]);
        }
    }
}

// ---------------------------------------------------------------------------
// Scores GEMM (NT, single-pass fp16, causal): P = SCALE * Q @ K^T, fp32 out.
// ---------------------------------------------------------------------------
__global__ __launch_bounds__(256)
void gemm_scores(const __half* __restrict__ Qh, const __half* __restrict__ Kh,
                 float* __restrict__ P)
{
    constexpr int ASZ = 128 * ASTR;
    constexpr int STG = 2 * ASZ;
    extern __shared__ __half smemh[];

    const int m0 = blockIdx.y * 128;
    const int n0 = blockIdx.x * 128;
    if (n0 > m0 + 127) return;

    const long zoff = (long)blockIdx.z * SEQ * DIM;
    Qh += zoff; Kh += zoff;
    P += (long)blockIdx.z * SEQ * SEQ;

    const int tid  = threadIdx.x;
    const int lane = tid & 31;
    const int wm   = ((tid >> 5) & 3) * 32;
    const int wn   = (tid >> 7) * 64;
    const bool active = (n0 + wn) <= (m0 + wm + 31);

    uint32_t aS[NSTG], bS[NSTG];
    #pragma unroll
    for (int s = 0; s < NSTG; ++s) {
        uint32_t base = smem_u32(smemh + s * STG);
        aS[s] = base;
        bS[s] = base + ASZ * 2;
    }

    auto issue = [&](int kt, int s) {
        if (kt < DIM) {
            #pragma unroll
            for (int i = 0; i < 2; ++i) {
                int q = tid + i * 256;
                int r = q >> 2, c = (q & 3) * 8;
                uint32_t doff = (uint32_t)(r * ASTR + c) * 2;
                cpa16(aS[s] + doff, Qh + (long)(m0 + r) * DIM + kt + c);
                cpa16(bS[s] + doff, Kh + (long)(n0 + r) * DIM + kt + c);
            }
        }
        CP_COMMIT();
    };

    ACC_DECL();
    issue(0, 0);
    issue(32, 1);

    int s = 0;
    for (int kt = 0; kt < DIM; kt += 32) {
        CP_WAIT1();
        __syncthreads();
        issue(kt + 64, (s + 2) % NSTG);
        if (active)
            mma_tile1<true>(acc, aS[s], bS[s], wm, wn, lane);
        s = (s + 1) % NSTG;
        __syncthreads();
    }

    if (active) {
        #pragma unroll
        for (int mt = 0; mt < 2; ++mt) {
            #pragma unroll
            for (int nt = 0; nt < 8; ++nt) {
                int row = m0 + wm + mt * 16 + (lane >> 2);
                int col = n0 + wn + nt * 8 + (lane & 3) * 2;
                float* f = acc[mt][nt];
                *(float2*)(P + (long)row * SEQ + col) =
                    make_float2(SCALE * f[0], SCALE * f[1]);
                *(float2*)(P + (long)(row + 8) * SEQ + col) =
                    make_float2(SCALE * f[2], SCALE * f[3]);
            }
        }
    }
}

// ---------------------------------------------------------------------------
// PV GEMM (NN, single-pass fp16, K bounded): out = P @ V, fp32 out.
// ---------------------------------------------------------------------------
__global__ __launch_bounds__(256)
void gemm_pv(const __half* __restrict__ Ph, const __half* __restrict__ Vh,
             float* __restrict__ Out)
{
    constexpr int ASZ = 128 * ASTR;
    constexpr int BSZ = 32 * BSTR;
    constexpr int STG = ASZ + BSZ;
    extern __shared__ __half smemh[];

    const int m0 = blockIdx.y * 128;
    const int n0 = blockIdx.x * 128;

    Ph += (long)blockIdx.z * SEQ * SEQ;
    Vh += (long)blockIdx.z * SEQ * DIM;
    Out += (long)blockIdx.z * SEQ * DIM;

    const int tid  = threadIdx.x;
    const int lane = tid & 31;
    const int wm   = ((tid >> 5) & 3) * 32;
    const int wn   = (tid >> 7) * 64;
    const int kEnd = m0 + 128;   // P zero beyond diagonal

    uint32_t aS[NSTG], bS[NSTG];
    #pragma unroll
    for (int s = 0; s < NSTG; ++s) {
        uint32_t base = smem_u32(smemh + s * STG);
        aS[s] = base;
        bS[s] = base + ASZ * 2;
    }

    auto issue = [&](int kt, int s) {
        if (kt < kEnd) {
            #pragma unroll
            for (int i = 0; i < 2; ++i) {
                int q = tid + i * 256;
                int r = q >> 2, c = (q & 3) * 8;
                uint32_t doff = (uint32_t)(r * ASTR + c) * 2;
                cpa16(aS[s] + doff, Ph + (long)(m0 + r) * SEQ + kt + c);
                int kk = q >> 4, nn = (q & 15) * 8;
                uint32_t boff = (uint32_t)(kk * BSTR + nn) * 2;
                cpa16(bS[s] + boff, Vh + (long)(kt + kk) * DIM + n0 + nn);
            }
        }
        CP_COMMIT();
    };

    ACC_DECL();
    issue(0, 0);
    issue(32, 1);

    int s = 0;
    for (int kt = 0; kt < kEnd; kt += 32) {
        CP_WAIT1();
        __syncthreads();
        issue(kt + 64, (s + 2) % NSTG);
        mma_tile1<false>(acc, aS[s], bS[s], wm, wn, lane);
        s = (s + 1) % NSTG;
        __syncthreads();
    }

    #pragma unroll
    for (int mt = 0; mt < 2; ++mt) {
        #pragma unroll
        for (int nt = 0; nt < 8; ++nt) {
            int row = m0 + wm + mt * 16 + (lane >> 2);
            int col = n0 + wn + nt * 8 + (lane & 3) * 2;
            float* f = acc[mt][nt];
            *(float2*)(Out + (long)row * DIM + col) = make_float2(f[0], f[1]);
            *(float2*)(Out + (long)(row + 8) * DIM + col) = make_float2(f[2], f[3]);
        }
    }
}

// ---------------------------------------------------------------------------
// Causal softmax: fp32 scores -> fp16 normalized probabilities (zeros past diag)
// ---------------------------------------------------------------------------
__global__ __launch_bounds__(256)
void softmax_causal(const float* __restrict__ P, __half* __restrict__ Ph)
{
    const int S = SEQ;
    const int i = blockIdx.x, b = blockIdx.y;
    const float* row = P + ((long)b * S + i) * S;
    __half* hrow = Ph + ((long)b * S + i) * S;

    __shared__ float buf[SEQ];
    __shared__ float red[256];
    const int tid = threadIdx.x;
    const int L = i + 1;

    float m = -3.0e38f;
    for (int j = tid; j < L; j += 256) {
        float v = row[j];
        buf[j] = v;
        m = fmaxf(m, v);
    }
    red[tid] = m;
    __syncthreads();
    #pragma unroll
    for (int sd = 128; sd > 0; sd >>= 1) {
        if (tid < sd) red[tid] = fmaxf(red[tid], red[tid + sd]);
        __syncthreads();
    }
    m = red[0];
    __syncthreads();

    float sum = 0.f;
    for (int j = tid; j < L; j += 256) {
        float e = expf(buf[j] - m);
        buf[j] = e;
        sum += e;
    }
    red[tid] = sum;
    __syncthreads();
    #pragma unroll
    for (int sd = 128; sd > 0; sd >>= 1) {
        if (tid < sd) red[tid] += red[tid + sd];
        __syncthreads();
    }
    const float inv = 1.0f / red[0];

    for (int j = tid; j < S; j += 256) {
        float v = (j < L) ? buf[j] * inv : 0.f;
        hrow[j] = __float2half_rn(v);
    }
}

// ---------------------------------------------------------------------------
extern "C" void kernel_launch(void* const* d_in, const int* in_sizes, int n_in,
                              void* d_out, int out_size)
{
    (void)in_sizes; (void)n_in; (void)out_size;
    const float* X  = (const float*)d_in[0];
    const float* Wq = (const float*)d_in[1];
    const float* Wk = (const float*)d_in[2];
    const float* Wv = (const float*)d_in[3];
    float* out = (float*)d_out;

    #define SYM(v, s) void* v; cudaGetSymbolAddress(&v, s)
    SYM(pP, g_P);
    SYM(pXh, g_Xhi); SYM(pXl, g_Xlo);
    SYM(pWqh, g_Wqh); SYM(pWql, g_Wql);
    SYM(pWkh, g_Wkh); SYM(pWkl, g_Wkl);
    SYM(pWvh, g_Wvh); SYM(pWvl, g_Wvl);
    SYM(pQh, g_Qh); SYM(pKh, g_Kh); SYM(pVh, g_Vh); SYM(pPh, g_Ph);
    #undef SYM

    const int QKV_SMEM = NSTG * (2 * 128 * ASTR + 2 * 32 * BSTR) * 2;  // 113664
    const int SC_SMEM  = NSTG * (2 * 128 * ASTR) * 2;                   // 61440
    const int PV_SMEM  = NSTG * (128 * ASTR + 32 * BSTR) * 2;           // 56832

    cudaFuncSetAttribute(gemm_qkv, cudaFuncAttributeMaxDynamicSharedMemorySize,
                         QKV_SMEM);
    cudaFuncSetAttribute(gemm_scores, cudaFuncAttributeMaxDynamicSharedMemorySize,
                         SC_SMEM);
    cudaFuncSetAttribute(gemm_pv, cudaFuncAttributeMaxDynamicSharedMemorySize,
                         PV_SMEM);

    // 0) split X and weights to bf16 hi/lo
    {
        long nX = (long)BATCH * SEQ * HID / 4;
        split_fp32<<<2048, 256>>>(X, (bf16*)pXh, (bf16*)pXl, nX);
        long nW = (long)HID * DIM / 4;
        split_fp32<<<512, 256>>>(Wq, (bf16*)pWqh, (bf16*)pWql, nW);
        split_fp32<<<512, 256>>>(Wk, (bf16*)pWkh, (bf16*)pWkl, nW);
        split_fp32<<<512, 256>>>(Wv, (bf16*)pWvh, (bf16*)pWvl, nW);
    }

    // 1) merged QKV projections (3-term bf16) -> fp16 Q, K, V
    {
        dim3 grid(24, (BATCH * SEQ) / 128, 1);
        gemm_qkv<<<grid, 256, QKV_SMEM>>>(
            (bf16*)pXh, (bf16*)pXl,
            (bf16*)pWqh, (bf16*)pWql, (bf16*)pWkh, (bf16*)pWkl,
            (bf16*)pWvh, (bf16*)pWvl,
            (__half*)pQh, (__half*)pKh, (__half*)pVh);
    }

    // 2) scores = SCALE * Q @ K^T (single-pass fp16), causal blocks only
    {
        dim3 grid(SEQ / 128, SEQ / 128, BATCH);
        gemm_scores<<<grid, 256, SC_SMEM>>>(
            (__half*)pQh, (__half*)pKh, (float*)pP);
    }

    // 3) causal softmax -> fp16 normalized probabilities
    {
        dim3 grid(SEQ, BATCH);
        softmax_causal<<<grid, 256>>>((float*)pP, (__half*)pPh);
    }

    // 4) out = P @ V (single-pass fp16), K bounded by causality
    {
        dim3 grid(DIM / 128, SEQ / 128, BATCH);
        gemm_pv<<<grid, 256, PV_SMEM>>>(
            (__half*)pPh, (__half*)pVh, out);
    }
}

// round 12
// speedup vs baseline: 6.9961x; 1.5840x over previous
#include <cuda_runtime.h>
#include <cuda_fp16.h>
#include <cstdint>
#include <math.h>

#define BATCH 4
#define SEQ   2048
#define HID   1024
#define DIM   1024
#define SCALE 0.03125f   // 1/sqrt(1024)

// Scratch (device globals; runtime allocation is forbidden)
__device__ float  g_P [(long)BATCH * SEQ * SEQ];
__device__ __half g_Xh[(long)BATCH * SEQ * HID];
__device__ __half g_Wh[(long)3 * HID * DIM];     // Wq,Wk,Wv stacked, [H][D] each
__device__ __half g_Qh[(long)BATCH * SEQ * DIM];
__device__ __half g_Kh[(long)BATCH * SEQ * DIM];
__device__ __half g_Vh[(long)BATCH * SEQ * DIM];
__device__ __half g_Ph[(long)BATCH * SEQ * SEQ];

// ---------------------------------------------------------------------------
// PTX helpers (baseline sm_80-level PTX)
// ---------------------------------------------------------------------------
__device__ __forceinline__ uint32_t smem_u32(const void* p) {
    uint32_t a;
    asm("{ .reg .u64 t; cvta.to.shared.u64 t, %1; cvt.u32.u64 %0, t; }"
        : "=r"(a) : "l"(p));
    return a;
}
__device__ __forceinline__ void cpa16(uint32_t dst, const void* src) {
    asm volatile("cp.async.cg.shared.global [%0], [%1], 16;" :: "r"(dst), "l"(src));
}
#define CP_COMMIT() asm volatile("cp.async.commit_group;" ::: "memory")
#define CP_WAIT1()  asm volatile("cp.async.wait_group 1;" ::: "memory")

__device__ __forceinline__ void ldsm_x4(uint32_t* r, uint32_t addr) {
    asm volatile("ldmatrix.sync.aligned.m8n8.x4.shared.b16 {%0,%1,%2,%3}, [%4];"
                 : "=r"(r[0]), "=r"(r[1]), "=r"(r[2]), "=r"(r[3]) : "r"(addr));
}
__device__ __forceinline__ void ldsm_x4_t(uint32_t* r, uint32_t addr) {
    asm volatile("ldmatrix.sync.aligned.m8n8.x4.trans.shared.b16 {%0,%1,%2,%3}, [%4];"
                 : "=r"(r[0]), "=r"(r[1]), "=r"(r[2]), "=r"(r[3]) : "r"(addr));
}
__device__ __forceinline__ void mma_f16(float* c, const uint32_t* a,
                                        const uint32_t* b) {
    asm volatile(
        "mma.sync.aligned.m16n8k16.row.col.f32.f16.f16.f32 "
        "{%0,%1,%2,%3}, {%4,%5,%6,%7}, {%8,%9}, {%0,%1,%2,%3};"
        : "+f"(c[0]), "+f"(c[1]), "+f"(c[2]), "+f"(c[3])
        : "r"(a[0]), "r"(a[1]), "r"(a[2]), "r"(a[3]), "r"(b[0]), "r"(b[1]));
}

// ---------------------------------------------------------------------------
// fp32 -> fp16 quantize, elementwise (n multiple of 4)
// ---------------------------------------------------------------------------
__global__ __launch_bounds__(256)
void quant_half(const float* __restrict__ src, __half* __restrict__ dst, long n4)
{
    long i = blockIdx.x * 256 + threadIdx.x;
    long stride = (long)gridDim.x * 256;
    for (; i < n4; i += stride) {
        float4 v = *(const float4*)(src + i * 4);
        __half2 h0 = __floats2half2_rn(v.x, v.y);
        __half2 h1 = __floats2half2_rn(v.z, v.w);
        uint2 u;
        u.x = reinterpret_cast<uint32_t&>(h0);
        u.y = reinterpret_cast<uint32_t&>(h1);
        *(uint2*)(dst + i * 4) = u;
    }
}

// ---------------------------------------------------------------------------
// Tiling config: BM=BN=128, BK=32, 256 threads, 8 warps (4m x 2n),
// warp tile 32x64. 3-stage cp.async pipeline. Single-pass fp16 everywhere.
// ---------------------------------------------------------------------------
#define ASTR 40    // 16-bit row stride A / B(NT): 80B, ldmatrix conflict-free
#define BSTR 136   // 16-bit row stride B(NN) [k][n]: 272B, conflict-free
#define NSTG 3

// single-pass fp16 tile over one staged k-chunk
template <bool TRANSB>
__device__ __forceinline__ void mma_tile1(
    float acc[2][8][4], uint32_t aS, uint32_t bS, int wm, int wn, int lane)
{
    #pragma unroll
    for (int ks = 0; ks < 2; ++ks) {
        uint32_t aF[2][4];
        #pragma unroll
        for (int mt = 0; mt < 2; ++mt) {
            uint32_t off =
                ((uint32_t)(wm + mt * 16 + (lane & 15)) * ASTR +
                 ks * 16 + (lane >> 4) * 8) * 2;
            ldsm_x4(aF[mt], aS + off);
        }
        #pragma unroll
        for (int np = 0; np < 4; ++np) {
            uint32_t bF[4];
            if (TRANSB) {
                uint32_t nrow = wn + np * 16 + (lane & 7) + (lane >> 4) * 8;
                uint32_t off = (nrow * ASTR + ks * 16 + ((lane >> 3) & 1) * 8) * 2;
                ldsm_x4(bF, bS + off);
            } else {
                uint32_t krow = ks * 16 + (lane & 15);
                uint32_t ncol = wn + np * 16 + (lane >> 4) * 8;
                uint32_t off = (krow * BSTR + ncol) * 2;
                ldsm_x4_t(bF, bS + off);
            }
            #pragma unroll
            for (int h = 0; h < 2; ++h) {
                #pragma unroll
                for (int mt = 0; mt < 2; ++mt)
                    mma_f16(acc[mt][np * 2 + h], aF[mt], bF + h * 2);
            }
        }
    }
}

#define ACC_DECL()                                                          \
    float acc[2][8][4];                                                     \
    _Pragma("unroll")                                                       \
    for (int i_ = 0; i_ < 2; ++i_)                                          \
        _Pragma("unroll")                                                   \
        for (int j_ = 0; j_ < 8; ++j_)                                      \
            _Pragma("unroll")                                               \
            for (int t_ = 0; t_ < 4; ++t_) acc[i_][j_][t_] = 0.f;

// ---------------------------------------------------------------------------
// Merged QKV projection (single-pass fp16, NN): grid (24, 64).
// bx>>3 selects W slab / output. Writes fp16 Q/K/V.
// ---------------------------------------------------------------------------
__global__ __launch_bounds__(256)
void gemm_qkv(const __half* __restrict__ Xh, const __half* __restrict__ Wh,
              __half* __restrict__ Qh, __half* __restrict__ Kh,
              __half* __restrict__ Vh)
{
    constexpr int ASZ = 128 * ASTR;
    constexpr int BSZ = 32 * BSTR;
    constexpr int STG = ASZ + BSZ;
    extern __shared__ __half smemh[];

    const int wsel = blockIdx.x >> 3;
    const int n0 = (blockIdx.x & 7) * 128;
    const int m0 = blockIdx.y * 128;

    const __half* Bh = Wh + (long)wsel * HID * DIM;
    __half* Out = (wsel == 0) ? Qh : (wsel == 1) ? Kh : Vh;

    const int tid  = threadIdx.x;
    const int lane = tid & 31;
    const int wm   = ((tid >> 5) & 3) * 32;
    const int wn   = (tid >> 7) * 64;

    uint32_t aS[NSTG], bS[NSTG];
    #pragma unroll
    for (int s = 0; s < NSTG; ++s) {
        uint32_t base = smem_u32(smemh + s * STG);
        aS[s] = base;
        bS[s] = base + ASZ * 2;
    }

    auto issue = [&](int kt, int s) {
        if (kt < HID) {
            #pragma unroll
            for (int i = 0; i < 2; ++i) {
                int q = tid + i * 256;
                int r = q >> 2, c = (q & 3) * 8;
                uint32_t doff = (uint32_t)(r * ASTR + c) * 2;
                cpa16(aS[s] + doff, Xh + (long)(m0 + r) * HID + kt + c);
                int kk = q >> 4, nn = (q & 15) * 8;
                uint32_t boff = (uint32_t)(kk * BSTR + nn) * 2;
                cpa16(bS[s] + boff, Bh + (long)(kt + kk) * DIM + n0 + nn);
            }
        }
        CP_COMMIT();
    };

    ACC_DECL();
    issue(0, 0);
    issue(32, 1);

    int s = 0;
    for (int kt = 0; kt < HID; kt += 32) {
        CP_WAIT1();
        __syncthreads();
        issue(kt + 64, (s + 2) % NSTG);
        mma_tile1<false>(acc, aS[s], bS[s], wm, wn, lane);
        s = (s + 1) % NSTG;
        __syncthreads();
    }

    #pragma unroll
    for (int mt = 0; mt < 2; ++mt) {
        #pragma unroll
        for (int nt = 0; nt < 8; ++nt) {
            int row = m0 + wm + mt * 16 + (lane >> 2);
            int col = n0 + wn + nt * 8 + (lane & 3) * 2;
            float* f = acc[mt][nt];
            *(__half2*)(Out + (long)row * DIM + col) =
                __floats2half2_rn(f[0], f[1]);
            *(__half2*)(Out + (long)(row + 8) * DIM + col) =
                __floats2half2_rn(f[2], f[3]);
        }
    }
}

// ---------------------------------------------------------------------------
// Scores GEMM (NT fp16, causal): P = SCALE * Q @ K^T, fp32 out.
// ---------------------------------------------------------------------------
__global__ __launch_bounds__(256)
void gemm_scores(const __half* __restrict__ Qh, const __half* __restrict__ Kh,
                 float* __restrict__ P)
{
    constexpr int ASZ = 128 * ASTR;
    constexpr int STG = 2 * ASZ;
    extern __shared__ __half smemh[];

    const int m0 = blockIdx.y * 128;
    const int n0 = blockIdx.x * 128;
    if (n0 > m0 + 127) return;

    const long zoff = (long)blockIdx.z * SEQ * DIM;
    Qh += zoff; Kh += zoff;
    P += (long)blockIdx.z * SEQ * SEQ;

    const int tid  = threadIdx.x;
    const int lane = tid & 31;
    const int wm   = ((tid >> 5) & 3) * 32;
    const int wn   = (tid >> 7) * 64;
    const bool active = (n0 + wn) <= (m0 + wm + 31);

    uint32_t aS[NSTG], bS[NSTG];
    #pragma unroll
    for (int s = 0; s < NSTG; ++s) {
        uint32_t base = smem_u32(smemh + s * STG);
        aS[s] = base;
        bS[s] = base + ASZ * 2;
    }

    auto issue = [&](int kt, int s) {
        if (kt < DIM) {
            #pragma unroll
            for (int i = 0; i < 2; ++i) {
                int q = tid + i * 256;
                int r = q >> 2, c = (q & 3) * 8;
                uint32_t doff = (uint32_t)(r * ASTR + c) * 2;
                cpa16(aS[s] + doff, Qh + (long)(m0 + r) * DIM + kt + c);
                cpa16(bS[s] + doff, Kh + (long)(n0 + r) * DIM + kt + c);
            }
        }
        CP_COMMIT();
    };

    ACC_DECL();
    issue(0, 0);
    issue(32, 1);

    int s = 0;
    for (int kt = 0; kt < DIM; kt += 32) {
        CP_WAIT1();
        __syncthreads();
        issue(kt + 64, (s + 2) % NSTG);
        if (active)
            mma_tile1<true>(acc, aS[s], bS[s], wm, wn, lane);
        s = (s + 1) % NSTG;
        __syncthreads();
    }

    if (active) {
        #pragma unroll
        for (int mt = 0; mt < 2; ++mt) {
            #pragma unroll
            for (int nt = 0; nt < 8; ++nt) {
                int row = m0 + wm + mt * 16 + (lane >> 2);
                int col = n0 + wn + nt * 8 + (lane & 3) * 2;
                float* f = acc[mt][nt];
                *(float2*)(P + (long)row * SEQ + col) =
                    make_float2(SCALE * f[0], SCALE * f[1]);
                *(float2*)(P + (long)(row + 8) * SEQ + col) =
                    make_float2(SCALE * f[2], SCALE * f[3]);
            }
        }
    }
}

// ---------------------------------------------------------------------------
// PV GEMM (NN fp16, K bounded): out = P @ V, fp32 out.
// ---------------------------------------------------------------------------
__global__ __launch_bounds__(256)
void gemm_pv(const __half* __restrict__ Ph, const __half* __restrict__ Vh,
             float* __restrict__ Out)
{
    constexpr int ASZ = 128 * ASTR;
    constexpr int BSZ = 32 * BSTR;
    constexpr int STG = ASZ + BSZ;
    extern __shared__ __half smemh[];

    const int m0 = blockIdx.y * 128;
    const int n0 = blockIdx.x * 128;

    Ph += (long)blockIdx.z * SEQ * SEQ;
    Vh += (long)blockIdx.z * SEQ * DIM;
    Out += (long)blockIdx.z * SEQ * DIM;

    const int tid  = threadIdx.x;
    const int lane = tid & 31;
    const int wm   = ((tid >> 5) & 3) * 32;
    const int wn   = (tid >> 7) * 64;
    const int kEnd = m0 + 128;   // P zero beyond diagonal

    uint32_t aS[NSTG], bS[NSTG];
    #pragma unroll
    for (int s = 0; s < NSTG; ++s) {
        uint32_t base = smem_u32(smemh + s * STG);
        aS[s] = base;
        bS[s] = base + ASZ * 2;
    }

    auto issue = [&](int kt, int s) {
        if (kt < kEnd) {
            #pragma unroll
            for (int i = 0; i < 2; ++i) {
                int q = tid + i * 256;
                int r = q >> 2, c = (q & 3) * 8;
                uint32_t doff = (uint32_t)(r * ASTR + c) * 2;
                cpa16(aS[s] + doff, Ph + (long)(m0 + r) * SEQ + kt + c);
                int kk = q >> 4, nn = (q & 15) * 8;
                uint32_t boff = (uint32_t)(kk * BSTR + nn) * 2;
                cpa16(bS[s] + boff, Vh + (long)(kt + kk) * DIM + n0 + nn);
            }
        }
        CP_COMMIT();
    };

    ACC_DECL();
    issue(0, 0);
    issue(32, 1);

    int s = 0;
    for (int kt = 0; kt < kEnd; kt += 32) {
        CP_WAIT1();
        __syncthreads();
        issue(kt + 64, (s + 2) % NSTG);
        mma_tile1<false>(acc, aS[s], bS[s], wm, wn, lane);
        s = (s + 1) % NSTG;
        __syncthreads();
    }

    #pragma unroll
    for (int mt = 0; mt < 2; ++mt) {
        #pragma unroll
        for (int nt = 0; nt < 8; ++nt) {
            int row = m0 + wm + mt * 16 + (lane >> 2);
            int col = n0 + wn + nt * 8 + (lane & 3) * 2;
            float* f = acc[mt][nt];
            *(float2*)(Out + (long)row * DIM + col) = make_float2(f[0], f[1]);
            *(float2*)(Out + (long)(row + 8) * DIM + col) = make_float2(f[2], f[3]);
        }
    }
}

// ---------------------------------------------------------------------------
// Causal softmax: fp32 scores -> fp16 normalized probabilities (zeros past diag)
// ---------------------------------------------------------------------------
__global__ __launch_bounds__(256)
void softmax_causal(const float* __restrict__ P, __half* __restrict__ Ph)
{
    const int S = SEQ;
    const int i = blockIdx.x, b = blockIdx.y;
    const float* row = P + ((long)b * S + i) * S;
    __half* hrow = Ph + ((long)b * S + i) * S;

    __shared__ float buf[SEQ];
    __shared__ float red[256];
    const int tid = threadIdx.x;
    const int L = i + 1;

    float m = -3.0e38f;
    for (int j = tid; j < L; j += 256) {
        float v = row[j];
        buf[j] = v;
        m = fmaxf(m, v);
    }
    red[tid] = m;
    __syncthreads();
    #pragma unroll
    for (int sd = 128; sd > 0; sd >>= 1) {
        if (tid < sd) red[tid] = fmaxf(red[tid], red[tid + sd]);
        __syncthreads();
    }
    m = red[0];
    __syncthreads();

    float sum = 0.f;
    for (int j = tid; j < L; j += 256) {
        float e = expf(buf[j] - m);
        buf[j] = e;
        sum += e;
    }
    red[tid] = sum;
    __syncthreads();
    #pragma unroll
    for (int sd = 128; sd > 0; sd >>= 1) {
        if (tid < sd) red[tid] += red[tid + sd];
        __syncthreads();
    }
    const float inv = 1.0f / red[0];

    for (int j = tid; j < S; j += 256) {
        float v = (j < L) ? buf[j] * inv : 0.f;
        hrow[j] = __float2half_rn(v);
    }
}

// ---------------------------------------------------------------------------
extern "C" void kernel_launch(void* const* d_in, const int* in_sizes, int n_in,
                              void* d_out, int out_size)
{
    (void)in_sizes; (void)n_in; (void)out_size;
    const float* X  = (const float*)d_in[0];
    const float* Wq = (const float*)d_in[1];
    const float* Wk = (const float*)d_in[2];
    const float* Wv = (const float*)d_in[3];
    float* out = (float*)d_out;

    #define SYM(v, s) void* v; cudaGetSymbolAddress(&v, s)
    SYM(pP, g_P); SYM(pXh, g_Xh); SYM(pWh, g_Wh);
    SYM(pQh, g_Qh); SYM(pKh, g_Kh); SYM(pVh, g_Vh); SYM(pPh, g_Ph);
    #undef SYM

    const int NN_SMEM = NSTG * (128 * ASTR + 32 * BSTR) * 2;   // 56832 B
    const int NT_SMEM = NSTG * (2 * 128 * ASTR) * 2;           // 61440 B

    cudaFuncSetAttribute(gemm_qkv, cudaFuncAttributeMaxDynamicSharedMemorySize,
                         NN_SMEM);
    cudaFuncSetAttribute(gemm_scores, cudaFuncAttributeMaxDynamicSharedMemorySize,
                         NT_SMEM);
    cudaFuncSetAttribute(gemm_pv, cudaFuncAttributeMaxDynamicSharedMemorySize,
                         NN_SMEM);

    // 0) quantize X and stacked W to fp16
    {
        long nX = (long)BATCH * SEQ * HID / 4;
        quant_half<<<2048, 256>>>(X, (__half*)pXh, nX);
        long nW = (long)HID * DIM / 4;
        quant_half<<<512, 256>>>(Wq, (__half*)pWh, nW);
        quant_half<<<512, 256>>>(Wk, (__half*)pWh + (long)HID * DIM, nW);
        quant_half<<<512, 256>>>(Wv, (__half*)pWh + 2L * HID * DIM, nW);
    }

    // 1) merged QKV projections (single-pass fp16) -> fp16 Q, K, V
    {
        dim3 grid(24, (BATCH * SEQ) / 128, 1);
        gemm_qkv<<<grid, 256, NN_SMEM>>>(
            (__half*)pXh, (__half*)pWh,
            (__half*)pQh, (__half*)pKh, (__half*)pVh);
    }

    // 2) scores = SCALE * Q @ K^T (fp16), causal blocks only
    {
        dim3 grid(SEQ / 128, SEQ / 128, BATCH);
        gemm_scores<<<grid, 256, NT_SMEM>>>(
            (__half*)pQh, (__half*)pKh, (float*)pP);
    }

    // 3) causal softmax -> fp16 normalized probabilities
    {
        dim3 grid(SEQ, BATCH);
        softmax_causal<<<grid, 256>>>((float*)pP, (__half*)pPh);
    }

    // 4) out = P @ V (fp16), K bounded by causality
    {
        dim3 grid(DIM / 128, SEQ / 128, BATCH);
        gemm_pv<<<grid, 256, NN_SMEM>>>(
            (__half*)pPh, (__half*)pVh, out);
    }
}